// round 3
// baseline (speedup 1.0000x reference)
#include <cuda_runtime.h>
#include <cuda_bf16.h>

// Problem constants (fixed by the reference).
#define B_DIM 64
#define H_DIM 512
#define W_DIM 640
#define P_DIM 100000
#define TOTAL (B_DIM * P_DIM)          // 6,400,000 points
#define HW    (H_DIM * W_DIM)          // 327,680
#define MARGIN_F 1.0f

__global__ void rd_init_out(float* out) {
    if (threadIdx.x == 0) out[0] = 0.0f;
}

__global__ __launch_bounds__(256) void rd_loss_kernel(
    const float* __restrict__ depth,
    const int*   __restrict__ xA,
    const int*   __restrict__ yA,
    const int*   __restrict__ xB,
    const int*   __restrict__ yB,
    const int*   __restrict__ ord,
    float* __restrict__ out)
{
    const float inv_n = 1.0f / (float)TOTAL;
    float acc = 0.0f;

    // 4 points per thread via int4. P % 4 == 0, so the 4 consecutive points
    // of a vec always belong to the same batch -> one divide per vec.
    const int nvec = TOTAL / 4;
    for (int v = blockIdx.x * blockDim.x + threadIdx.x; v < nvec;
         v += gridDim.x * blockDim.x)
    {
        const int idx0 = v * 4;
        const int b = idx0 / P_DIM;
        const float* __restrict__ base = depth + (long long)b * HW;

        const int4 vxA = __ldg((const int4*)(xA)  + v);
        const int4 vyA = __ldg((const int4*)(yA)  + v);
        const int4 vxB = __ldg((const int4*)(xB)  + v);
        const int4 vyB = __ldg((const int4*)(yB)  + v);
        const int4 vod = __ldg((const int4*)(ord) + v);

        const int xa[4] = {vxA.x, vxA.y, vxA.z, vxA.w};
        const int ya[4] = {vyA.x, vyA.y, vyA.z, vyA.w};
        const int xb[4] = {vxB.x, vxB.y, vxB.z, vxB.w};
        const int yb[4] = {vyB.x, vyB.y, vyB.z, vyB.w};
        const int od[4] = {vod.x, vod.y, vod.z, vod.w};

        // Batch the 8 gathers first for MLP (outstanding loads overlap).
        float zA[4], zB[4];
#pragma unroll
        for (int k = 0; k < 4; k++) {
            zA[k] = __ldg(base + ya[k] * W_DIM + xa[k]);
            zB[k] = __ldg(base + yb[k] * W_DIM + xb[k]);
        }

#pragma unroll
        for (int k = 0; k < 4; k++) {
            const float gt   = (float)(od[k] - 1);      // in {-1,0,1}
            const float mask = fabsf(gt);
            const float zd   = zA[k] - zB[k];
            const float t    = fminf(gt * zd, MARGIN_F);
            const float l1   = __logf(1.0f + __expf(-t));
            const float l2   = fmaxf(zd * zd, MARGIN_F * MARGIN_F);
            acc += mask * l1 + (1.0f - mask) * l2;
        }
    }

    // Block reduction: warp shuffle, then smem across warps.
    __shared__ float warp_sums[8];
    const int lane = threadIdx.x & 31;
    const int wid  = threadIdx.x >> 5;
#pragma unroll
    for (int off = 16; off > 0; off >>= 1)
        acc += __shfl_xor_sync(0xFFFFFFFF, acc, off);
    if (lane == 0) warp_sums[wid] = acc;
    __syncthreads();
    if (wid == 0) {
        float s = (lane < (blockDim.x >> 5)) ? warp_sums[lane] : 0.0f;
#pragma unroll
        for (int off = 4; off > 0; off >>= 1)
            s += __shfl_xor_sync(0xFFFFFFFF, s, off);
        if (lane == 0) atomicAdd(out, s * inv_n);
    }
}

extern "C" void kernel_launch(void* const* d_in, const int* in_sizes, int n_in,
                              void* d_out, int out_size)
{
    const float* depth = (const float*)d_in[0];
    const int*   xA    = (const int*)d_in[1];
    const int*   yA    = (const int*)d_in[2];
    const int*   xB    = (const int*)d_in[3];
    const int*   yB    = (const int*)d_in[4];
    const int*   ord   = (const int*)d_in[5];
    float* out = (float*)d_out;

    rd_init_out<<<1, 32>>>(out);

    const int threads = 256;
    const int nvec = TOTAL / 4;                       // 1,600,000
    int blocks = (nvec + threads - 1) / threads;      // 6250
    rd_loss_kernel<<<blocks, threads>>>(depth, xA, yA, xB, yB, ord, out);
}